// round 12
// baseline (speedup 1.0000x reference)
#include <cuda_runtime.h>
#include <cuda_fp16.h>
#include <cstdint>
#include <math.h>

#define Bb 128
#define Rr 1152
#define CI 8
#define Cc 10
#define Oo 16
#define NS  (Cc*Bb*Oo)   /* 20480 */
#define RT 16
#define NRT (Rr/RT)      /* 72 */
#define NIT 1280         /* k_it CTA count */
#define DEPTH 6
#define CHB 2048         /* chunk bytes: 128 thr * 16B */
#define NCHUNK 18        /* 36864 / 2048 */

// Static device scratch.
__device__ __half g_uh[(size_t)Cc*Bb*Rr*Oo];  // 47 MB, u in fp16
__device__ float  g_S[NS];                    // current s[c][b][o]
__device__ float  g_V[NS];                    // accumulated V (pre-scaled log2e)
__device__ float  g_n2a[640];                 // sum-sq partials after s1
__device__ float  g_n2b[NIT];                 // after iter-2
__device__ float  g_n2c[NIT];                 // after iter-3

// ---------------------------------------------------------------------------
// f32x2 packed helpers
// ---------------------------------------------------------------------------
typedef unsigned long long ull;
__device__ __forceinline__ ull pk2(float lo, float hi) {
    ull r; asm("mov.b64 %0, {%1, %2};" : "=l"(r) : "f"(lo), "f"(hi)); return r;
}
__device__ __forceinline__ void upk2(ull v, float& lo, float& hi) {
    asm("mov.b64 {%0, %1}, %2;" : "=f"(lo), "=f"(hi) : "l"(v));
}
__device__ __forceinline__ ull fma2(ull a, ull b, ull c) {
    ull r; asm("fma.rn.f32x2 %0, %1, %2, %3;" : "=l"(r) : "l"(a), "l"(b), "l"(c)); return r;
}
__device__ __forceinline__ ull add2(ull a, ull b) {
    ull r; asm("add.rn.f32x2 %0, %1, %2;" : "=l"(r) : "l"(a), "l"(b)); return r;
}

// ---------------------------------------------------------------------------
// mbarrier helpers
// ---------------------------------------------------------------------------
__device__ __forceinline__ uint32_t smem_u32(const void* p) {
    return (uint32_t)__cvta_generic_to_shared(p);
}
__device__ __forceinline__ void mbar_init(uint32_t a, uint32_t cnt) {
    asm volatile("mbarrier.init.shared.b64 [%0], %1;" :: "r"(a), "r"(cnt) : "memory");
}
__device__ __forceinline__ void mbar_expect_tx(uint32_t a, uint32_t bytes) {
    asm volatile("mbarrier.arrive.expect_tx.shared.b64 _, [%0], %1;"
                 :: "r"(a), "r"(bytes) : "memory");
}
__device__ __forceinline__ void mbar_arrive(uint32_t a) {
    asm volatile("mbarrier.arrive.shared.b64 _, [%0];" :: "r"(a) : "memory");
}
__device__ __forceinline__ void mbar_wait(uint32_t a, uint32_t parity) {
    asm volatile(
        "{\n\t"
        ".reg .pred P;\n\t"
        "WL_%=:\n\t"
        "mbarrier.try_wait.parity.acquire.cta.shared::cta.b64 P, [%0], %1, 0x989680;\n\t"
        "@P bra.uni WD_%=;\n\t"
        "bra.uni WL_%=;\n\t"
        "WD_%=:\n\t"
        "}" :: "r"(a), "r"(parity) : "memory");
}
__device__ __forceinline__ void bulk_cp(uint32_t dst, const void* src,
                                        uint32_t bytes, uint32_t mbar) {
    asm volatile(
        "cp.async.bulk.shared::cluster.global.mbarrier::complete_tx::bytes "
        "[%0], [%1], %2, [%3];"
        :: "r"(dst), "l"(src), "r"(bytes), "r"(mbar) : "memory");
}

// ---------------------------------------------------------------------------
// k_u: u[c,b,r,o] = sum_i x[b,r,i]*W[c,r,i,o] -> fp16. Pure compute (R5).
// ---------------------------------------------------------------------------
__global__ __launch_bounds__(128) void k_u(const float* __restrict__ x,
                                           const float* __restrict__ W)
{
    const int rt  = blockIdx.x, c = blockIdx.y;
    const int tid = threadIdx.x;
    const int o2  = tid & 7;
    const int rl  = tid >> 3;
    const int r   = rt * RT + rl;

    float w0[8], w1[8];
    {
        const float* Wp = W + (((size_t)c*Rr + r)*CI)*Oo + 2*o2;
        #pragma unroll
        for (int i = 0; i < 8; i++) {
            float2 v = *(const float2*)(Wp + i*Oo);
            w0[i] = v.x; w1[i] = v.y;
        }
    }

    const float4* xp = (const float4*)x;
    const size_t  xstep = (size_t)Rr*CI/4;
    const size_t  xbase = (size_t)r*CI/4;

    half2* udst = (half2*)g_uh + ((size_t)c*Bb*Rr + r)*8 + o2;

    float4 xa = xp[xbase], xb = xp[xbase+1];
    for (int b = 0; b < Bb; b++) {
        float4 na, nb;
        if (b + 1 < Bb) {
            size_t nx = xbase + (size_t)(b+1)*xstep;
            na = xp[nx]; nb = xp[nx+1];
        }
        float u0, u1;
        u0 =           xa.x*w0[0];        u1 =           xa.x*w1[0];
        u0 = fmaf(xa.y, w0[1], u0);       u1 = fmaf(xa.y, w1[1], u1);
        u0 = fmaf(xa.z, w0[2], u0);       u1 = fmaf(xa.z, w1[2], u1);
        u0 = fmaf(xa.w, w0[3], u0);       u1 = fmaf(xa.w, w1[3], u1);
        u0 = fmaf(xb.x, w0[4], u0);       u1 = fmaf(xb.x, w1[4], u1);
        u0 = fmaf(xb.y, w0[5], u0);       u1 = fmaf(xb.y, w1[5], u1);
        u0 = fmaf(xb.z, w0[6], u0);       u1 = fmaf(xb.z, w1[6], u1);
        u0 = fmaf(xb.w, w0[7], u0);       u1 = fmaf(xb.w, w1[7], u1);
        udst[(size_t)b*Rr*8] = __floats2half2_rn(u0, u1);
        xa = na; xb = nb;
    }
}

// ---------------------------------------------------------------------------
// k_s0: s1[cb,o] = mean_r u; per-CTA sum s1^2 -> g_n2a[640]. (R5-proven)
// ---------------------------------------------------------------------------
__global__ __launch_bounds__(256) void k_s0()
{
    const int bx = blockIdx.x, c = blockIdx.y;
    const int tid = threadIdx.x;
    __shared__ float ss[8*256];
    __shared__ float pA[256];
    __shared__ float shn[256];

    float qacc = 0.f;
    for (int bb = 0; bb < 2; bb++) {
        const int cb = c*Bb + bx*2 + bb;
        const float4* up = (const float4*)(g_uh + (size_t)cb*Rr*Oo);

        float s[8];
        #pragma unroll
        for (int j = 0; j < 8; j++) s[j] = 0.f;
        #pragma unroll
        for (int k = 0; k < 9; k++) {
            float4 raw = up[tid + k*256];
            const half2* hp = (const half2*)&raw;
            #pragma unroll
            for (int j = 0; j < 4; j++) {
                float2 f2 = __half22float2(hp[j]);
                s[2*j]   += f2.x;
                s[2*j+1] += f2.y;
            }
        }
        const int row = (tid >> 1) + (tid & 1)*128;
        #pragma unroll
        for (int j = 0; j < 8; j++) ss[j*256 + row] = s[j];
        __syncthreads();
        {
            const int h = tid >> 7, col = (tid >> 4) & 7, grp = tid & 15;
            float a = 0.f;
            #pragma unroll
            for (int i = 0; i < 8; i++) a += ss[col*256 + h*128 + grp + 16*i];
            pA[tid] = a;
        }
        __syncthreads();
        if (tid < 16) {
            const int h = tid >> 3, col = tid & 7;
            float st = 0.f;
            #pragma unroll
            for (int g2 = 0; g2 < 16; g2++) st += pA[h*128 + col*16 + g2];
            const float sn = st * (1.0f / (float)Rr);
            g_S[cb*16 + tid] = sn;
            qacc += sn * sn;
        }
        __syncthreads();
    }
    shn[tid] = qacc;
    __syncthreads();
    if (tid == 0) {
        float t = 0.f;
        #pragma unroll
        for (int i = 0; i < 16; i++) t += shn[i];
        g_n2a[blockIdx.y*gridDim.x + blockIdx.x] = t;
    }
}

// ---------------------------------------------------------------------------
// k_it: cp.async.bulk (UBLKCP) + mbarrier 6-stage ring. Single elected
// producer thread; consumers only wait/LDS/compute/arrive. 18 chunks = 3
// exact ring rounds -> compile-time parities.
// ---------------------------------------------------------------------------
__global__ __launch_bounds__(128) void k_it(const float* __restrict__ n2part,
                                            int nn,
                                            float* __restrict__ n2out,
                                            int iter3)
{
    __shared__ __align__(16) char ring[DEPTH*CHB];       // 12 KB
    __shared__ __align__(8) unsigned long long mb_full[DEPTH], mb_empty[DEPTH];
    __shared__ float shn[128];

    const int cb  = blockIdx.y*Bb + blockIdx.x;
    const int tid = threadIdx.x;
    const int lane = tid & 31;
    const int p   = (tid & 1) * 8;
    const char* src = (const char*)(g_uh + (size_t)cb*Rr*Oo);
    const int toff = tid*16;
    const uint32_t ring_a = smem_u32(ring);

    uint32_t fullA[DEPTH], emptyA[DEPTH];
    #pragma unroll
    for (int s = 0; s < DEPTH; s++) {
        fullA[s]  = smem_u32(&mb_full[s]);
        emptyA[s] = smem_u32(&mb_empty[s]);
    }

    if (tid == 0) {
        #pragma unroll
        for (int s = 0; s < DEPTH; s++) {
            mbar_init(fullA[s], 1);
            mbar_init(emptyA[s], 4);     // one arrive per warp
        }
        asm volatile("fence.proxy.async.shared::cta;" ::: "memory");
        // prologue: fill all 6 stages
        #pragma unroll
        for (int s = 0; s < DEPTH; s++) {
            mbar_expect_tx(fullA[s], CHB);
            bulk_cp(ring_a + s*CHB, src + s*CHB, CHB, fullA[s]);
        }
    }
    // overlap with in-flight bulk copies: global n2 -> K
    float acc = 0.f;
    for (int i = tid; i < nn; i += 128) acc += n2part[i];
    shn[tid] = acc;
    __syncthreads();        // also publishes mbarrier init to all threads
    for (int st = 64; st > 0; st >>= 1) {
        if (tid < st) shn[tid] += shn[tid + st];
        __syncthreads();
    }
    const float n2 = shn[0];
    const float K  = (sqrtf(n2) / (1.0f + n2)) * 1.4426950408889634f;

    ull V2[4];
    #pragma unroll
    for (int j = 0; j < 4; j++) {
        const int i0 = cb*16 + p + 2*j;
        float v0 = K * g_S[i0],   v1 = K * g_S[i0+1];
        if (iter3) { v0 += g_V[i0]; v1 += g_V[i0+1]; }
        V2[j] = pk2(v0, v1);
    }
    if (!iter3 && tid < 16) g_V[cb*16 + tid] = K * g_S[cb*16 + tid];

    const ull MAGIC2  = pk2(12582912.0f, 12582912.0f);
    const ull NMAGIC2 = pk2(-12582912.0f, -12582912.0f);
    const ull CF4 = pk2(0.0096181298f, 0.0096181298f);
    const ull CF3 = pk2(0.0555041087f, 0.0555041087f);
    const ull CF2 = pk2(0.2402265070f, 0.2402265070f);
    const ull CF1 = pk2(0.6931471806f, 0.6931471806f);
    const ull CF0 = pk2(1.0f, 1.0f);
    const ull SIGN64 = 0x8000000080000000ULL;

    ull z2[4], s2[4];
    #pragma unroll
    for (int j = 0; j < 4; j++) { z2[j] = 0ULL; s2[j] = 0ULL; }

    #pragma unroll
    for (int k = 0; k < NCHUNK; k++) {
        const int s = k % DEPTH;
        const uint32_t cph = (k / DEPTH) & 1;       // full parity (compile-time)
        mbar_wait(fullA[s], cph);
        float4 cur = *(const float4*)(ring + s*CHB + toff);
        const half2* hp = (const half2*)&cur;
        #pragma unroll
        for (int j = 0; j < 4; j++) {
            float2 fu = __half22float2(hp[j]);
            ull u2 = pk2(fu.x, fu.y);
            ull t2 = fma2(u2, V2[j], MAGIC2);
            ull g2 = add2(t2, NMAGIC2);
            ull f2 = fma2(u2, V2[j], g2 ^ SIGN64);
            ull p2 = fma2(CF4, f2, CF3);
            p2 = fma2(p2, f2, CF2);
            p2 = fma2(p2, f2, CF1);
            p2 = fma2(p2, f2, CF0);
            float tlo, thi, plo, phi;
            upk2(t2, tlo, thi);
            upk2(p2, plo, phi);
            float e0 = __int_as_float(__float_as_int(plo) + (__float_as_int(tlo) << 23));
            float e1 = __int_as_float(__float_as_int(phi) + (__float_as_int(thi) << 23));
            ull e2 = pk2(e0, e1);
            z2[j] = add2(z2[j], e2);
            s2[j] = fma2(e2, u2, s2[j]);
        }
        __syncwarp();
        if (lane == 0) mbar_arrive(emptyA[s]);      // release: LDS done
        if (tid == 0 && k + DEPTH < NCHUNK) {
            const uint32_t eph = (k >= DEPTH) ? 1u : 0u;   // compile-time
            mbar_wait(emptyA[s], eph);               // all 4 warps arrived
            mbar_expect_tx(fullA[s], CHB);
            bulk_cp(ring_a + s*CHB, src + (k + DEPTH)*CHB, CHB, fullA[s]);
        }
    }

    float z[8], s[8];
    #pragma unroll
    for (int j = 0; j < 4; j++) {
        upk2(z2[j], z[2*j], z[2*j+1]);
        upk2(s2[j], s[2*j], s[2*j+1]);
    }

    // epilogue reductions alias into the drained ring
    __syncthreads();
    float* zs  = (float*)ring;           // 8*132 = 4224 B
    float* ssm = zs  + 8*132;            // 4224 B
    float* pAz = ssm + 8*132;            // 512 B
    float* pAs = pAz + 128;              // 512 B

    const int row = (tid >> 1) + (tid & 1)*64;
    #pragma unroll
    for (int j = 0; j < 8; j++) { zs[j*132 + row] = z[j]; ssm[j*132 + row] = s[j]; }
    __syncthreads();
    {
        const int h = tid >> 6, col = (tid >> 3) & 7, grp = tid & 7;
        float az = 0.f, as = 0.f;
        #pragma unroll
        for (int i = 0; i < 8; i++) {
            const int a = col*132 + h*64 + grp + 8*i;
            az += zs[a]; as += ssm[a];
        }
        pAz[tid] = az; pAs[tid] = as;
    }
    __syncthreads();
    float qacc = 0.f;
    if (tid < 16) {
        const int h = tid >> 3, col = tid & 7;
        float zt = 0.f, st = 0.f;
        #pragma unroll
        for (int g = 0; g < 8; g++) {
            const int a = h*64 + col*8 + g;
            zt += pAz[a]; st += pAs[a];
        }
        const float sn = st / zt;
        g_S[cb*16 + tid] = sn;
        qacc = sn * sn;
    }
    shn[tid] = qacc;
    __syncthreads();
    if (tid == 0) {
        float t = 0.f;
        #pragma unroll
        for (int i = 0; i < 16; i++) t += shn[i];
        n2out[blockIdx.y*gridDim.x + blockIdx.x] = t;
    }
}

// ---------------------------------------------------------------------------
// k_fin: out = f3 * s3. grid 20 x 1024.
// ---------------------------------------------------------------------------
__global__ __launch_bounds__(1024) void k_fin(float* __restrict__ outp)
{
    const int tid = threadIdx.x;
    __shared__ float sh[1024];
    float acc = g_n2c[tid];
    if (tid < NIT - 1024) acc += g_n2c[1024 + tid];
    sh[tid] = acc;
    __syncthreads();
    for (int st = 512; st > 0; st >>= 1) {
        if (tid < st) sh[tid] += sh[tid + st];
        __syncthreads();
    }
    const float n2 = sh[0];
    const float f  = sqrtf(n2) / (1.0f + n2);
    const int i = blockIdx.x*1024 + tid;
    outp[i] = f * g_S[i];
}

// ---------------------------------------------------------------------------
extern "C" void kernel_launch(void* const* d_in, const int* in_sizes, int n_in,
                              void* d_out, int out_size)
{
    const float* x = (const float*)d_in[0];   // [128,1152,8]
    const float* W = (const float*)d_in[1];   // [10,1152,8,16]
    float* out = (float*)d_out;               // 20480 floats
    (void)in_sizes; (void)n_in; (void)out_size;

    float *n2a, *n2b, *n2c;
    cudaGetSymbolAddress((void**)&n2a, g_n2a);
    cudaGetSymbolAddress((void**)&n2b, g_n2b);
    cudaGetSymbolAddress((void**)&n2c, g_n2c);

    k_u  <<<dim3(NRT, Cc), 128>>>(x, W);
    k_s0 <<<dim3(Bb/2, Cc), 256>>>();                   // iter 1 + n2
    k_it <<<dim3(Bb, Cc), 128>>>(n2a,  640, n2b, 0);    // iter 2
    k_it <<<dim3(Bb, Cc), 128>>>(n2b, NIT, n2c, 1);     // iter 3
    k_fin<<<20, 1024>>>(out);                           // final squash
}

// round 16
// speedup vs baseline: 1.1873x; 1.1873x over previous
#include <cuda_runtime.h>
#include <cuda_fp16.h>
#include <cuda_pipeline.h>
#include <cstdint>
#include <math.h>

#define Bb 128
#define Rr 1152
#define CI 8
#define Cc 10
#define Oo 16
#define NS  (Cc*Bb*Oo)   /* 20480 */
#define RT 16
#define NRT (Rr/RT)      /* 72 */
#define DEPTH 6
#define CHB 2048         /* chunk bytes: 128 thr * 16B */
#define NCHUNK 9         /* half tile: 18432 / 2048 */

// Static device scratch.
__device__ __half g_uh[(size_t)Cc*Bb*Rr*Oo];  // 47 MB, u in fp16
__device__ float  g_S[NS];                    // current s[c][b][o]
__device__ float  g_V[NS];                    // accumulated V (pre-scaled log2e)
__device__ float  g_zp[NS*2];                 // per-half partial z
__device__ float  g_sp[NS*2];                 // per-half partial s
__device__ float  g_n2a[640];                 // sum-sq partials after s1
__device__ float  g_n2b[20];                  // after iter-2
__device__ float  g_n2c[20];                  // after iter-3

// ---------------------------------------------------------------------------
// f32x2 packed helpers
// ---------------------------------------------------------------------------
typedef unsigned long long ull;
__device__ __forceinline__ ull pk2(float lo, float hi) {
    ull r; asm("mov.b64 %0, {%1, %2};" : "=l"(r) : "f"(lo), "f"(hi)); return r;
}
__device__ __forceinline__ void upk2(ull v, float& lo, float& hi) {
    asm("mov.b64 {%0, %1}, %2;" : "=f"(lo), "=f"(hi) : "l"(v));
}
__device__ __forceinline__ ull fma2(ull a, ull b, ull c) {
    ull r; asm("fma.rn.f32x2 %0, %1, %2, %3;" : "=l"(r) : "l"(a), "l"(b), "l"(c)); return r;
}
__device__ __forceinline__ ull add2(ull a, ull b) {
    ull r; asm("add.rn.f32x2 %0, %1, %2;" : "=l"(r) : "l"(a), "l"(b)); return r;
}

// ---------------------------------------------------------------------------
// k_u: u[c,b,r,o] = sum_i x[b,r,i]*W[c,r,i,o] -> fp16. Pure compute (R5).
// ---------------------------------------------------------------------------
__global__ __launch_bounds__(128) void k_u(const float* __restrict__ x,
                                           const float* __restrict__ W)
{
    const int rt  = blockIdx.x, c = blockIdx.y;
    const int tid = threadIdx.x;
    const int o2  = tid & 7;
    const int rl  = tid >> 3;
    const int r   = rt * RT + rl;

    float w0[8], w1[8];
    {
        const float* Wp = W + (((size_t)c*Rr + r)*CI)*Oo + 2*o2;
        #pragma unroll
        for (int i = 0; i < 8; i++) {
            float2 v = *(const float2*)(Wp + i*Oo);
            w0[i] = v.x; w1[i] = v.y;
        }
    }

    const float4* xp = (const float4*)x;
    const size_t  xstep = (size_t)Rr*CI/4;
    const size_t  xbase = (size_t)r*CI/4;

    half2* udst = (half2*)g_uh + ((size_t)c*Bb*Rr + r)*8 + o2;

    float4 xa = xp[xbase], xb = xp[xbase+1];
    for (int b = 0; b < Bb; b++) {
        float4 na, nb;
        if (b + 1 < Bb) {
            size_t nx = xbase + (size_t)(b+1)*xstep;
            na = xp[nx]; nb = xp[nx+1];
        }
        float u0, u1;
        u0 =           xa.x*w0[0];        u1 =           xa.x*w1[0];
        u0 = fmaf(xa.y, w0[1], u0);       u1 = fmaf(xa.y, w1[1], u1);
        u0 = fmaf(xa.z, w0[2], u0);       u1 = fmaf(xa.z, w1[2], u1);
        u0 = fmaf(xa.w, w0[3], u0);       u1 = fmaf(xa.w, w1[3], u1);
        u0 = fmaf(xb.x, w0[4], u0);       u1 = fmaf(xb.x, w1[4], u1);
        u0 = fmaf(xb.y, w0[5], u0);       u1 = fmaf(xb.y, w1[5], u1);
        u0 = fmaf(xb.z, w0[6], u0);       u1 = fmaf(xb.z, w1[6], u1);
        u0 = fmaf(xb.w, w0[7], u0);       u1 = fmaf(xb.w, w1[7], u1);
        udst[(size_t)b*Rr*8] = __floats2half2_rn(u0, u1);
        xa = na; xb = nb;
    }
}

// ---------------------------------------------------------------------------
// k_s0: s1[cb,o] = mean_r u; per-CTA sum s1^2 -> g_n2a[640]. (R5-proven)
// ---------------------------------------------------------------------------
__global__ __launch_bounds__(256) void k_s0()
{
    const int bx = blockIdx.x, c = blockIdx.y;
    const int tid = threadIdx.x;
    __shared__ float ss[8*256];
    __shared__ float pA[256];
    __shared__ float shn[256];

    float qacc = 0.f;
    for (int bb = 0; bb < 2; bb++) {
        const int cb = c*Bb + bx*2 + bb;
        const float4* up = (const float4*)(g_uh + (size_t)cb*Rr*Oo);

        float s[8];
        #pragma unroll
        for (int j = 0; j < 8; j++) s[j] = 0.f;
        #pragma unroll
        for (int k = 0; k < 9; k++) {
            float4 raw = up[tid + k*256];
            const half2* hp = (const half2*)&raw;
            #pragma unroll
            for (int j = 0; j < 4; j++) {
                float2 f2 = __half22float2(hp[j]);
                s[2*j]   += f2.x;
                s[2*j+1] += f2.y;
            }
        }
        const int row = (tid >> 1) + (tid & 1)*128;
        #pragma unroll
        for (int j = 0; j < 8; j++) ss[j*256 + row] = s[j];
        __syncthreads();
        {
            const int h = tid >> 7, col = (tid >> 4) & 7, grp = tid & 15;
            float a = 0.f;
            #pragma unroll
            for (int i = 0; i < 8; i++) a += ss[col*256 + h*128 + grp + 16*i];
            pA[tid] = a;
        }
        __syncthreads();
        if (tid < 16) {
            const int h = tid >> 3, col = tid & 7;
            float st = 0.f;
            #pragma unroll
            for (int g2 = 0; g2 < 16; g2++) st += pA[h*128 + col*16 + g2];
            const float sn = st * (1.0f / (float)Rr);
            g_S[cb*16 + tid] = sn;
            qacc += sn * sn;
        }
        __syncthreads();
    }
    shn[tid] = qacc;
    __syncthreads();
    if (tid == 0) {
        float t = 0.f;
        #pragma unroll
        for (int i = 0; i < 16; i++) t += shn[i];
        g_n2a[blockIdx.y*gridDim.x + blockIdx.x] = t;
    }
}

// ---------------------------------------------------------------------------
// k_it: SPLIT version — each CTA handles one r-HALF of one cb (9 chunks),
// doubling warps/SM vs R10. R10 ring (depth 6 x 2KB, barrier-free mainloop,
// each thread consumes its own bytes). Writes per-half z,s partials.
// iter3==0: V = K*s_prev (stored to g_V by half 0). iter3==1: V = g_V+K*s.
// grid (256, 10) = 2560 CTAs x 128 thr.
// ---------------------------------------------------------------------------
__global__ __launch_bounds__(128) void k_it(const float* __restrict__ n2part,
                                            int nn,
                                            int iter3)
{
    __shared__ __align__(16) char ring[DEPTH*CHB];   // 12 KB
    __shared__ float shn[128];

    const int tid  = threadIdx.x;
    const int cb   = blockIdx.y*Bb + (blockIdx.x >> 1);
    const int half = blockIdx.x & 1;
    const int p    = (tid & 1) * 8;
    const char* src = (const char*)(g_uh + (size_t)cb*Rr*Oo) + half*(NCHUNK*CHB);
    const int toff = tid*16;

    // prologue: issue first DEPTH chunks (one commit group per chunk)
    #pragma unroll
    for (int k = 0; k < DEPTH; k++) {
        __pipeline_memcpy_async(ring + k*CHB + toff, src + k*CHB + toff, 16);
        __pipeline_commit();
    }

    // overlap: global n2 -> K
    float acc = 0.f;
    for (int i = tid; i < nn; i += 128) acc += n2part[i];
    shn[tid] = acc;
    __syncthreads();
    for (int st = 64; st > 0; st >>= 1) {
        if (tid < st) shn[tid] += shn[tid + st];
        __syncthreads();
    }
    const float n2 = shn[0];
    const float K  = (sqrtf(n2) / (1.0f + n2)) * 1.4426950408889634f;

    ull V2[4];
    #pragma unroll
    for (int j = 0; j < 4; j++) {
        const int i0 = cb*16 + p + 2*j;
        float v0 = K * g_S[i0],   v1 = K * g_S[i0+1];
        if (iter3) { v0 += g_V[i0]; v1 += g_V[i0+1]; }
        V2[j] = pk2(v0, v1);
    }
    if (!iter3 && half == 0 && tid < 16) g_V[cb*16 + tid] = K * g_S[cb*16 + tid];

    const ull MAGIC2  = pk2(12582912.0f, 12582912.0f);
    const ull NMAGIC2 = pk2(-12582912.0f, -12582912.0f);
    const ull CF4 = pk2(0.0096181298f, 0.0096181298f);
    const ull CF3 = pk2(0.0555041087f, 0.0555041087f);
    const ull CF2 = pk2(0.2402265070f, 0.2402265070f);
    const ull CF1 = pk2(0.6931471806f, 0.6931471806f);
    const ull CF0 = pk2(1.0f, 1.0f);
    const ull SIGN64 = 0x8000000080000000ULL;

    ull z2[4], s2[4];
    #pragma unroll
    for (int j = 0; j < 4; j++) { z2[j] = 0ULL; s2[j] = 0ULL; }

    // barrier-free pipelined mainloop (9 chunks)
    #pragma unroll
    for (int k = 0; k < NCHUNK; k++) {
        asm volatile("cp.async.wait_group 5;" ::: "memory");
        float4 cur = *(const float4*)(ring + (k % DEPTH)*CHB + toff);
        if (k + DEPTH < NCHUNK)
            __pipeline_memcpy_async(ring + (k % DEPTH)*CHB + toff,
                                    src + (k + DEPTH)*CHB + toff, 16);
        __pipeline_commit();
        const half2* hp = (const half2*)&cur;
        #pragma unroll
        for (int j = 0; j < 4; j++) {
            float2 fu = __half22float2(hp[j]);
            ull u2 = pk2(fu.x, fu.y);
            ull t2 = fma2(u2, V2[j], MAGIC2);
            ull g2 = add2(t2, NMAGIC2);
            ull f2 = fma2(u2, V2[j], g2 ^ SIGN64);
            ull p2 = fma2(CF4, f2, CF3);
            p2 = fma2(p2, f2, CF2);
            p2 = fma2(p2, f2, CF1);
            p2 = fma2(p2, f2, CF0);
            float tlo, thi, plo, phi;
            upk2(t2, tlo, thi);
            upk2(p2, plo, phi);
            float e0 = __int_as_float(__float_as_int(plo) + (__float_as_int(tlo) << 23));
            float e1 = __int_as_float(__float_as_int(phi) + (__float_as_int(thi) << 23));
            ull e2 = pk2(e0, e1);
            z2[j] = add2(z2[j], e2);
            s2[j] = fma2(e2, u2, s2[j]);
        }
    }

    float z[8], s[8];
    #pragma unroll
    for (int j = 0; j < 4; j++) {
        upk2(z2[j], z[2*j], z[2*j+1]);
        upk2(s2[j], s[2*j], s[2*j+1]);
    }

    // epilogue reductions alias into the drained ring -> per-half partials
    __syncthreads();
    float* zs  = (float*)ring;           // 8*132 = 4224 B
    float* ssm = zs  + 8*132;            // 4224 B
    float* pAz = ssm + 8*132;            // 512 B
    float* pAs = pAz + 128;              // 512 B

    const int row = (tid >> 1) + (tid & 1)*64;
    #pragma unroll
    for (int j = 0; j < 8; j++) { zs[j*132 + row] = z[j]; ssm[j*132 + row] = s[j]; }
    __syncthreads();
    {
        const int h = tid >> 6, col = (tid >> 3) & 7, grp = tid & 7;
        float az = 0.f, as = 0.f;
        #pragma unroll
        for (int i = 0; i < 8; i++) {
            const int a = col*132 + h*64 + grp + 8*i;
            az += zs[a]; as += ssm[a];
        }
        pAz[tid] = az; pAs[tid] = as;
    }
    __syncthreads();
    if (tid < 16) {
        const int h = tid >> 3, col = tid & 7;
        float zt = 0.f, st = 0.f;
        #pragma unroll
        for (int g = 0; g < 8; g++) {
            const int a = h*64 + col*8 + g;
            zt += pAz[a]; st += pAs[a];
        }
        g_zp[cb*32 + half*16 + tid] = zt;
        g_sp[cb*32 + half*16 + tid] = st;
    }
}

// ---------------------------------------------------------------------------
// k_c: combine halves: sn = (s0+s1)/(z0+z1) -> g_S; per-CTA sum sn^2 ->
// n2out[20]. grid 20 x 1024.
// ---------------------------------------------------------------------------
__global__ __launch_bounds__(1024) void k_c(float* __restrict__ n2out)
{
    const int tid = threadIdx.x;
    const int i   = blockIdx.x*1024 + tid;
    const int cb  = i >> 4, o = i & 15;
    const float zv = g_zp[cb*32 + o] + g_zp[cb*32 + 16 + o];
    const float sv = g_sp[cb*32 + o] + g_sp[cb*32 + 16 + o];
    const float sn = sv / zv;
    g_S[i] = sn;
    __shared__ float sh[1024];
    sh[tid] = sn*sn;
    __syncthreads();
    for (int st = 512; st > 0; st >>= 1) {
        if (tid < st) sh[tid] += sh[tid + st];
        __syncthreads();
    }
    if (tid == 0) n2out[blockIdx.x] = sh[0];
}

// ---------------------------------------------------------------------------
// k_fin: out = f3 * s3. grid 20 x 1024.
// ---------------------------------------------------------------------------
__global__ __launch_bounds__(1024) void k_fin(float* __restrict__ outp)
{
    const int tid = threadIdx.x;
    __shared__ float sh[1024];
    sh[tid] = (tid < 20) ? g_n2c[tid] : 0.f;
    __syncthreads();
    for (int st = 512; st > 0; st >>= 1) {
        if (tid < st) sh[tid] += sh[tid + st];
        __syncthreads();
    }
    const float n2 = sh[0];
    const float f  = sqrtf(n2) / (1.0f + n2);
    const int i = blockIdx.x*1024 + tid;
    outp[i] = f * g_S[i];
}

// ---------------------------------------------------------------------------
extern "C" void kernel_launch(void* const* d_in, const int* in_sizes, int n_in,
                              void* d_out, int out_size)
{
    const float* x = (const float*)d_in[0];   // [128,1152,8]
    const float* W = (const float*)d_in[1];   // [10,1152,8,16]
    float* out = (float*)d_out;               // 20480 floats
    (void)in_sizes; (void)n_in; (void)out_size;

    float *n2a, *n2b, *n2c;
    cudaGetSymbolAddress((void**)&n2a, g_n2a);
    cudaGetSymbolAddress((void**)&n2b, g_n2b);
    cudaGetSymbolAddress((void**)&n2c, g_n2c);

    k_u  <<<dim3(NRT, Cc), 128>>>(x, W);
    k_s0 <<<dim3(Bb/2, Cc), 256>>>();               // iter 1 + n2
    k_it <<<dim3(Bb*2, Cc), 128>>>(n2a, 640, 0);    // iter 2 (split halves)
    k_c  <<<20, 1024>>>(n2b);                       // combine + n2
    k_it <<<dim3(Bb*2, Cc), 128>>>(n2b,  20, 1);    // iter 3 (split halves)
    k_c  <<<20, 1024>>>(n2c);                       // combine + n2
    k_fin<<<20, 1024>>>(out);                       // final squash
}